// round 12
// baseline (speedup 1.0000x reference)
#include <cuda_runtime.h>
#include <math.h>

// ---------------------------------------------------------------------------
// TextureBaker — 2 kernels, warp-autonomous bake.
//  1) tb_setup : per-triangle setup -> 48B record (+tri id), ids, bbox.
//  2) tb_bake  : WARP = 8x4 pixel tile (block = 256 threads = 8 independent
//       warps; no __syncthreads in the main loop). Per chunk of 64 triangles:
//         - 2 bbox tests per lane (coalesced float4)
//         - ballot + popc stable compaction into a warp-private smem segment
//         - per-pixel first-hit scan (early exit, FP expressions identical
//           to prior passing kernels)
//         - __all_sync break: P(first hit within 64 tris) ~ 0.994, so most
//           warps stop after one chunk; stragglers only block their own warp.
//  Bake launched with PDL; gates on cudaGridDependencySynchronize().
// ---------------------------------------------------------------------------

#define MAX_F  8192
#define TW     8       // warp tile width  (pixels)
#define TH     4       // warp tile height (pixels)
#define CH     64      // triangles per chunk (2 per lane)

__device__ float4 g_rec [MAX_F * 3];  // [ax ay v0x v0y][v1x v1y d00 d01][d11 inv tid 0]
__device__ int4   g_ids [MAX_F];
__device__ float4 g_bbox[MAX_F];      // (minx, maxx, miny, maxy)

// ------------------------------- setup ------------------------------------
__global__ void tb_setup_kernel(const float* __restrict__ uv,
                                const int*   __restrict__ fidx,
                                int nf)
{
    int t = blockIdx.x * blockDim.x + threadIdx.x;
    if (t >= nf) return;

    int i0 = fidx[3 * t + 0];
    int i1 = fidx[3 * t + 1];
    int i2 = fidx[3 * t + 2];

    float ax = uv[2 * i0], ay = uv[2 * i0 + 1];
    float bx = uv[2 * i1], by = uv[2 * i1 + 1];
    float cx = uv[2 * i2], cy = uv[2 * i2 + 1];

    float v0x = bx - ax, v0y = by - ay;
    float v1x = cx - ax, v1y = cy - ay;

    float d00 = v0x * v0x + v0y * v0y;
    float d01 = v0x * v1x + v0y * v1y;
    float d11 = v1x * v1x + v1y * v1y;
    float denom = d00 * d11 - d01 * d01;

    // Degenerate triangle -> NaN inv -> inside test always false (matches ref).
    float inv = (fabsf(denom) < 1e-12f) ? __int_as_float(0x7fc00000)
                                        : (1.0f / denom);

    g_rec[3 * t + 0] = make_float4(ax, ay, v0x, v0y);
    g_rec[3 * t + 1] = make_float4(v1x, v1y, d00, d01);
    g_rec[3 * t + 2] = make_float4(d11, inv, __int_as_float(t), 0.0f);
    g_ids[t] = make_int4(i0, i1, i2, 0);

    float4 bb;
    bb.x = fminf(ax, fminf(bx, cx));
    bb.y = fmaxf(ax, fmaxf(bx, cx));
    bb.z = fminf(ay, fminf(by, cy));
    bb.w = fmaxf(ay, fmaxf(by, cy));
    g_bbox[t] = bb;
}

// -------------------------------- bake ------------------------------------
__global__ void __launch_bounds__(256, 8)
tb_bake_kernel(const float* __restrict__ attr,
               int nf, int res,
               float* __restrict__ out)
{
    // warp-private record segments: 8 warps x 64 records x 48B = 24 KB
    __shared__ float4 s_rec[8][CH * 3];

    int tid  = threadIdx.x;
    int lane = tid & 31;
    int wid  = tid >> 5;
    unsigned lmask = (1u << lane) - 1u;

    // global warp id -> 8x4 pixel tile
    int gwarp = blockIdx.x * 8 + wid;
    int ntx = res / TW;                  // tiles across (res=512 -> 64)
    int wx = gwarp % ntx;
    int wy = gwarp / ntx;

    int col = wx * TW + (lane & (TW - 1));
    int row = wy * TH + (lane >> 3);
    bool valid = (col < res) && (row < res);

    const float eps = 1e-5f;
    float rinv = 1.0f / (float)res;
    float x0 = (float)(wx * TW)      * rinv - eps;
    float x1 = (float)(wx * TW + TW) * rinv + eps;
    float y0 = (float)(wy * TH)      * rinv - eps;
    float y1 = (float)(wy * TH + TH) * rinv + eps;

    float pxx = ((float)col + 0.5f) * rinv;
    float pxy = ((float)row + 0.5f) * rinv;

    int   hitT = -1;
    float u = 0.0f, v = 0.0f, w = 0.0f;
    bool  found = false;

    float4* wrec = &s_rec[wid][0];

    // PDL: wait for setup outputs before reading g_* arrays.
    cudaGridDependencySynchronize();

    for (int chunk = 0; chunk < nf; chunk += CH) {
        __syncwarp();   // protect wrec reuse across chunks

        // ---- bbox test: 2 triangles per lane (coalesced float4 loads) ----
        int t0 = chunk + lane;
        int t1 = t0 + 32;
        bool k0 = false, k1 = false;
        if (t0 < nf) {
            float4 bb = g_bbox[t0];
            k0 = !(bb.x > x1 || bb.y < x0 || bb.z > y1 || bb.w < y0);
        }
        if (t1 < nf) {
            float4 bb = g_bbox[t1];
            k1 = !(bb.x > x1 || bb.y < x0 || bb.z > y1 || bb.w < y0);
        }
        unsigned b0 = __ballot_sync(0xffffffffu, k0);
        unsigned b1 = __ballot_sync(0xffffffffu, k1);
        int n0 = __popc(b0);

        // ---- stable compaction into warp-private smem ----
        if (k0) {
            int p = __popc(b0 & lmask);
            wrec[3 * p + 0] = g_rec[3 * t0 + 0];
            wrec[3 * p + 1] = g_rec[3 * t0 + 1];
            wrec[3 * p + 2] = g_rec[3 * t0 + 2];
        }
        if (k1) {
            int p = n0 + __popc(b1 & lmask);
            wrec[3 * p + 0] = g_rec[3 * t1 + 0];
            wrec[3 * p + 1] = g_rec[3 * t1 + 1];
            wrec[3 * p + 2] = g_rec[3 * t1 + 2];
        }
        __syncwarp();
        int m = n0 + __popc(b1);

        // ---- per-pixel first-hit scan (early exit); index order preserved ----
        if (!found && valid) {
            for (int j = 0; j < m; j++) {
                float4 q0 = wrec[3 * j + 0];   // ax ay v0x v0y
                float4 q1 = wrec[3 * j + 1];   // v1x v1y d00 d01
                float4 q2 = wrec[3 * j + 2];   // d11 inv tid 0

                float v2x = pxx - q0.x;
                float v2y = pxy - q0.y;
                float d20 = v2x * q0.z + v2y * q0.w;
                float d21 = v2x * q1.x + v2y * q1.y;
                float vv  = (q2.x * d20 - q1.w * d21) * q2.y;
                float ww  = (q1.z * d21 - q1.w * d20) * q2.y;
                float uu  = 1.0f - vv - ww;
                if (uu >= 0.0f && vv >= 0.0f && ww >= 0.0f) {
                    found = true;
                    u = uu; v = vv; w = ww;
                    hitT = __float_as_int(q2.z);
                    break;
                }
            }
        }

        // warp-local exit: most warps are done after the first chunk
        if (__all_sync(0xffffffffu, found || !valid)) break;
    }

    if (!valid) return;

    float o0 = 0.0f, o1 = 0.0f, o2 = 0.0f;
    if (found) {
        int4 ids = g_ids[hitT];
        const float* a0 = attr + 3 * ids.x;
        const float* a1 = attr + 3 * ids.y;
        const float* a2 = attr + 3 * ids.z;
        o0 = u * a0[0] + v * a1[0] + w * a2[0];
        o1 = u * a0[1] + v * a1[1] + w * a2[1];
        o2 = u * a0[2] + v * a1[2] + w * a2[2];
    }

    int pix = row * res + col;
    out[3 * pix + 0] = o0;
    out[3 * pix + 1] = o1;
    out[3 * pix + 2] = o2;
}

// ------------------------------- launch -----------------------------------
extern "C" void kernel_launch(void* const* d_in, const int* in_sizes, int n_in,
                              void* d_out, int out_size)
{
    const float* attr = (const float*)d_in[0];
    const float* uv   = (const float*)d_in[1];
    const int*   fidx = (const int*)  d_in[2];
    float*       out  = (float*)      d_out;

    int nf = in_sizes[2] / 3;
    int nf_used = (nf / 64) * 64;          // reference truncates to chunks of 64
    if (nf_used > MAX_F) nf_used = MAX_F;

    int res = (int)(sqrt((double)out_size / 3.0) + 0.5);
    int ntx = (res + TW - 1) / TW;
    int nty = (res + TH - 1) / TH;
    long nwarps = (long)ntx * nty;
    int nblocks = (int)((nwarps + 7) / 8);

    if (nf_used > 0) {
        int sblocks = (nf_used + 127) / 128;
        tb_setup_kernel<<<sblocks, 128>>>(uv, fidx, nf_used);
    }

    // PDL launch: overlap bake prologue with setup.
    cudaLaunchConfig_t cfg = {};
    cfg.gridDim  = dim3((unsigned)nblocks, 1, 1);
    cfg.blockDim = dim3(256, 1, 1);
    cfg.dynamicSmemBytes = 0;
    cfg.stream = 0;
    cudaLaunchAttribute at[1];
    at[0].id = cudaLaunchAttributeProgrammaticStreamSerialization;
    at[0].val.programmaticStreamSerializationAllowed = 1;
    cfg.attrs = at;
    cfg.numAttrs = 1;
    cudaLaunchKernelEx(&cfg, tb_bake_kernel, attr, nf_used, res, out);
}